// round 8
// baseline (speedup 1.0000x reference)
#include <cuda_runtime.h>

#define BB 4
#define C 64
#define IC 16
#define H 128
#define W 128
#define DH 64
#define DW 64
#define NN 4096  // DH*DW

// ---------------- scratch (device globals; no allocation) ----------------
__device__ __align__(16) float g_q[BB*NN*IC];   // tf32(LOG2E*q) bits
__device__ __align__(16) float g_k[BB*IC*NN];   // transposed [b][ic][n], tf32 bits
__device__ __align__(16) float g_v[BB*NN*IC];
__device__ __align__(16) float g_y[BB*IC*NN];
__device__ __align__(16) unsigned long long g_wpk[C*IC];  // out_w packed pairs
__device__ float g_sum[C];
__device__ float g_sqs[C];

typedef unsigned long long ull;
typedef unsigned int uint;

__device__ __forceinline__ ull pk2(float x, float y) {
    ull r;
    asm("mov.b64 %0, {%1,%2};" : "=l"(r) : "f"(x), "f"(y));
    return r;
}
__device__ __forceinline__ void upk2(ull v, float& lo, float& hi) {
    asm("mov.b64 {%0,%1}, %2;" : "=f"(lo), "=f"(hi) : "l"(v));
}
__device__ __forceinline__ void fma2(ull& d, ull a, ull b) {
    asm("fma.rn.f32x2 %0, %1, %2, %3;" : "=l"(d) : "l"(a), "l"(b), "l"(d));
}
__device__ __forceinline__ ull add2(ull a, ull b) {
    ull r;
    asm("add.rn.f32x2 %0, %1, %2;" : "=l"(r) : "l"(a), "l"(b));
    return r;
}
__device__ __forceinline__ float ex2f(float x) {
    float r;
    asm("ex2.approx.f32 %0, %1;" : "=f"(r) : "f"(x));
    return r;
}
__device__ __forceinline__ uint tf32c(float f) {
    uint r;
    asm("cvt.rna.tf32.f32 %0, %1;" : "=r"(r) : "f"(f));
    return r;
}
__device__ __forceinline__ void mma_tf32(float* c, const uint* a, uint b0, uint b1) {
    asm("mma.sync.aligned.m16n8k8.row.col.f32.tf32.tf32.f32 "
        "{%0,%1,%2,%3}, {%4,%5,%6,%7}, {%8,%9}, {%0,%1,%2,%3};"
        : "+f"(c[0]), "+f"(c[1]), "+f"(c[2]), "+f"(c[3])
        : "r"(a[0]), "r"(a[1]), "r"(a[2]), "r"(a[3]), "r"(b0), "r"(b1));
}
__device__ __forceinline__ void cpa16(uint dst, const void* src) {
    asm volatile("cp.async.ca.shared.global [%0], [%1], 16;" :: "r"(dst), "l"(src));
}

#define LOG2E 1.4426950408889634f

// ---------------- Kernel 1: downsample (odd-pixel pick) + Q/K/V projections ----------------
__global__ void qkv_kernel(const float* __restrict__ x,
                           const float* __restrict__ g_w,  const float* __restrict__ g_b,
                           const float* __restrict__ th_w, const float* __restrict__ th_b,
                           const float* __restrict__ ph_w, const float* __restrict__ ph_b) {
    __shared__ float xd_s[C][32];
    __shared__ float w_s[48][C];
    __shared__ float b_s[48];
    int b = blockIdx.y, tile = blockIdx.x, tid = threadIdx.x;

    for (int idx = tid; idx < 48 * C; idx += 128) {
        int o = idx >> 6, c = idx & 63;
        float w;
        if (o < 16)      w = th_w[o * C + c];
        else if (o < 32) w = ph_w[(o - 16) * C + c];
        else             w = g_w[(o - 32) * C + c];
        w_s[o][c] = w;
    }
    if (tid < 48)
        b_s[tid] = (tid < 16) ? th_b[tid] : ((tid < 32) ? ph_b[tid - 16] : g_b[tid - 32]);

    int n0 = tile * 32;
    for (int idx = tid; idx < C * 32; idx += 128) {
        int c = idx >> 5, p = idx & 31;
        int n = n0 + p;
        int i = n >> 6, j = n & 63;
        xd_s[c][p] = x[(((b * C + c) * H + 2 * i + 1) * W) + 2 * j + 1];
    }
    __syncthreads();

    int p = tid & 31, og = tid >> 5;
    int n = n0 + p;
    #pragma unroll
    for (int r = 0; r < 12; r++) {
        int o = og + 4 * r;
        float a0 = b_s[o], a1 = 0.f, a2 = 0.f, a3 = 0.f;
        #pragma unroll
        for (int c = 0; c < C; c += 4) {
            a0 = fmaf(w_s[o][c + 0], xd_s[c + 0][p], a0);
            a1 = fmaf(w_s[o][c + 1], xd_s[c + 1][p], a1);
            a2 = fmaf(w_s[o][c + 2], xd_s[c + 2][p], a2);
            a3 = fmaf(w_s[o][c + 3], xd_s[c + 3][p], a3);
        }
        float acc = (a0 + a1) + (a2 + a3);
        if (o < 16)      g_q[(b * NN + n) * IC + o] = __uint_as_float(tf32c(acc * LOG2E));
        else if (o < 32) g_k[(b * IC + (o - 16)) * NN + n] = __uint_as_float(tf32c(acc));
        else             g_v[(b * NN + n) * IC + (o - 32)] = acc;
    }
}

// ---------------- Kernel 1b: zero BN stats (also spaces launches so attn is #4) ----------------
__global__ void prep_zero() {
    int t = threadIdx.x;
    if (t < C) { g_sum[t] = 0.f; g_sqs[t] = 0.f; }
}

// ---------------- Kernel 1c: pack out_w into broadcast pairs ----------------
__global__ void prep_pack(const float* __restrict__ out_w) {
    int i = blockIdx.x * 256 + threadIdx.x;   // 1024 entries
    float w = out_w[i];
    g_wpk[i] = pk2(w, w);
}

// ---------------- Kernel 2: tensor-core flash attention, cp.async double-buffered ----------------
// grid (64, BB), block 256 (8 warps), 3 CTAs/SM. CTA = 64 queries.
#define TK 128
#define KSP 136
__global__ __launch_bounds__(256, 3) void attn_kernel() {
    __shared__ uint  ks[2][IC][KSP];                // K tf32 bits, [ic][key]
    __shared__ __align__(16) float vs[2][TK][20];   // V rows, padded
    __shared__ float redY[2][64][17];
    __shared__ float redD[2][64];

    int b = blockIdx.y;
    int t = threadIdx.x;
    int w = t >> 5, lane = t & 31;
    int qw = w & 3, kh = w >> 2;
    int r = lane >> 2, cc = lane & 3;
    int n0 = blockIdx.x * 64;

    // A fragments (Q) — pre-scaled + tf32-rounded by qkv_kernel
    uint A0[4], A1[4];
    {
        const uint* qb = (const uint*)(g_q + (b * NN + n0 + qw * 16) * IC);
        A0[0] = qb[ r      * IC + cc     ];
        A0[1] = qb[(r + 8) * IC + cc     ];
        A0[2] = qb[ r      * IC + cc + 4 ];
        A0[3] = qb[(r + 8) * IC + cc + 4 ];
        A1[0] = qb[ r      * IC + cc + 8 ];
        A1[1] = qb[(r + 8) * IC + cc + 8 ];
        A1[2] = qb[ r      * IC + cc + 12];
        A1[3] = qb[(r + 8) * IC + cc + 12];
    }

    float Y0[4] = {0.f, 0.f, 0.f, 0.f};
    float Y1[4] = {0.f, 0.f, 0.f, 0.f};
    float denr = 0.f, dens = 0.f;

    const float* kb = g_k + b * IC * NN;
    const float* vb = g_v + b * NN * IC;

    int kc0 = t, kc1 = t + 256;
    int ic0s = kc0 >> 5, col0 = kc0 & 31;
    int ic1s = kc1 >> 5, col1 = kc1 & 31;
    int vkey0 = t >> 2, vseg0 = t & 3;
    int vkey1 = (t + 256) >> 2, vseg1 = t & 3;

    uint ks_d0[2], ks_d1[2], vs_d0[2], vs_d1[2];
    #pragma unroll
    for (int bf = 0; bf < 2; bf++) {
        ks_d0[bf] = (uint)__cvta_generic_to_shared(&ks[bf][ic0s][col0 * 4]);
        ks_d1[bf] = (uint)__cvta_generic_to_shared(&ks[bf][ic1s][col1 * 4]);
        vs_d0[bf] = (uint)__cvta_generic_to_shared(&vs[bf][vkey0][vseg0 * 4]);
        vs_d1[bf] = (uint)__cvta_generic_to_shared(&vs[bf][vkey1][vseg1 * 4]);
    }

    cpa16(ks_d0[0], kb + ic0s * NN + col0 * 4);
    cpa16(ks_d1[0], kb + ic1s * NN + col1 * 4);
    cpa16(vs_d0[0], vb + vkey0 * IC + vseg0 * 4);
    cpa16(vs_d1[0], vb + vkey1 * IC + vseg1 * 4);
    asm volatile("cp.async.commit_group;");

    for (int it = 0; it < NN / TK; it++) {
        int cur = it & 1;
        if (it < NN / TK - 1) {
            int nxt = cur ^ 1, kt = (it + 1) * TK;
            cpa16(ks_d0[nxt], kb + ic0s * NN + kt + col0 * 4);
            cpa16(ks_d1[nxt], kb + ic1s * NN + kt + col1 * 4);
            cpa16(vs_d0[nxt], vb + (kt + vkey0) * IC + vseg0 * 4);
            cpa16(vs_d1[nxt], vb + (kt + vkey1) * IC + vseg1 * 4);
            asm volatile("cp.async.commit_group;");
            asm volatile("cp.async.wait_group 1;");
        } else {
            asm volatile("cp.async.wait_group 0;");
        }
        __syncthreads();

        #pragma unroll
        for (int nt = 0; nt < 8; nt++) {
            int key0 = kh * 64 + nt * 8;
            float S[4] = {0.f, 0.f, 0.f, 0.f};
            mma_tf32(S, A0, ks[cur][cc][key0 + r],     ks[cur][cc + 4][key0 + r]);
            mma_tf32(S, A1, ks[cur][cc + 8][key0 + r], ks[cur][cc + 12][key0 + r]);

            float e0 = ex2f(S[0]);
            float e1 = ex2f(S[1]);
            float e2 = ex2f(S[2]);
            float e3 = ex2f(S[3]);
            denr += e0 + e1;
            dens += e2 + e3;

            uint P[4];
            P[0] = __float_as_uint(e0);
            P[1] = __float_as_uint(e2);
            P[2] = __float_as_uint(e1);
            P[3] = __float_as_uint(e3);
            int ka = key0 + 2 * cc;
            mma_tf32(Y0, P, __float_as_uint(vs[cur][ka][r]),
                            __float_as_uint(vs[cur][ka + 1][r]));
            mma_tf32(Y1, P, __float_as_uint(vs[cur][ka][r + 8]),
                            __float_as_uint(vs[cur][ka + 1][r + 8]));
        }
        __syncthreads();
    }

    denr += __shfl_xor_sync(0xffffffffu, denr, 1);
    denr += __shfl_xor_sync(0xffffffffu, denr, 2);
    dens += __shfl_xor_sync(0xffffffffu, dens, 1);
    dens += __shfl_xor_sync(0xffffffffu, dens, 2);

    {
        int q0 = qw * 16 + r, q1 = q0 + 8;
        redY[kh][q0][2 * cc]     = Y0[0];
        redY[kh][q0][2 * cc + 1] = Y0[1];
        redY[kh][q1][2 * cc]     = Y0[2];
        redY[kh][q1][2 * cc + 1] = Y0[3];
        redY[kh][q0][8 + 2 * cc]     = Y1[0];
        redY[kh][q0][8 + 2 * cc + 1] = Y1[1];
        redY[kh][q1][8 + 2 * cc]     = Y1[2];
        redY[kh][q1][8 + 2 * cc + 1] = Y1[3];
        if (cc == 0) {
            redD[kh][q0] = denr;
            redD[kh][q1] = dens;
        }
    }
    __syncthreads();

    {
        int q = t >> 2, ic = (t & 3) * 4;
        float inv = 1.0f / (redD[0][q] + redD[1][q]);
        #pragma unroll
        for (int j = 0; j < 4; j++) {
            float v = (redY[0][q][ic + j] + redY[1][q][ic + j]) * inv;
            g_y[(b * IC + ic + j) * NN + n0 + q] = v;
        }
    }
}

// ---------------- Kernel 3: upsample + out-proj + residual + BN stats ----------------
__global__ void fuse_kernel(const float* __restrict__ x,
                            const float* __restrict__ out_b,
                            float* __restrict__ out) {
    __shared__ __align__(8) float yup[IC][64];
    __shared__ ull wsm2[C][IC];
    __shared__ float bsm[C];
    int bx = blockIdx.x;
    int b  = bx >> 8;
    int row = (bx >> 1) & 127;
    int jh = bx & 1;
    int t = threadIdx.x;

    #pragma unroll
    for (int i = 0; i < 4; i++) {
        int idx = t + 256 * i;
        wsm2[idx >> 4][idx & 15] = g_wpk[idx];
    }
    if (t < C) bsm[t] = out_b[t];

    float fi = 0.5f * row - 0.5f;
    int r0 = (int)floorf(fi);
    float wi = fi - (float)r0;
    int r1 = min(r0 + 1, DH - 1);
    r0 = max(r0, 0);

    for (int idx = t; idx < IC * 64; idx += 256) {
        int ic = idx >> 6, p = idx & 63;
        int j = jh * 64 + p;
        float fj = 0.5f * j - 0.5f;
        int c0 = (int)floorf(fj);
        float wj = fj - (float)c0;
        int c1 = min(c0 + 1, DW - 1);
        c0 = max(c0, 0);
        const float* yp = g_y + (b * IC + ic) * NN;
        float v00 = yp[r0 * DW + c0], v01 = yp[r0 * DW + c1];
        float v10 = yp[r1 * DW + c0], v11 = yp[r1 * DW + c1];
        yup[ic][p] = (1.f - wi) * fmaf(wj, v01 - v00, v00)
                   +        wi  * fmaf(wj, v11 - v10, v10);
    }
    __syncthreads();

    int p2 = t & 31, cg = t >> 5;   // cg warp-uniform: warp handles channels cg*8..+7
    ull yv[16];
    #pragma unroll
    for (int i2 = 0; i2 < 16; i2++) yv[i2] = *(const ull*)&yup[i2][2 * p2];

    float s1v[8], s2v[8];
    #pragma unroll
    for (int k = 0; k < 8; k++) {
        int c = cg * 8 + k;
        float bb = bsm[c];
        ull acc = pk2(bb, bb);
        #pragma unroll
        for (int i2 = 0; i2 < 16; i2++) fma2(acc, wsm2[c][i2], yv[i2]);
        int gi = ((b * C + c) * H + row) * W + jh * 64 + 2 * p2;
        ull xv = *(const ull*)(x + gi);
        acc = add2(acc, xv);
        *(ull*)(out + gi) = acc;
        float lo, hi;
        upk2(acc, lo, hi);
        s1v[k] = lo + hi;
        s2v[k] = fmaf(lo, lo, hi * hi);
    }

    // warp-level BN stat reduction (channel-uniform warps) + global atomics
    #pragma unroll
    for (int k = 0; k < 8; k++) {
        #pragma unroll
        for (int off = 16; off; off >>= 1) {
            s1v[k] += __shfl_xor_sync(0xffffffffu, s1v[k], off);
            s2v[k] += __shfl_xor_sync(0xffffffffu, s2v[k], off);
        }
    }
    if (p2 == 0) {
        #pragma unroll
        for (int k = 0; k < 8; k++) {
            int c = cg * 8 + k;
            atomicAdd(&g_sum[c], s1v[k]);
            atomicAdd(&g_sqs[c], s2v[k]);
        }
    }
}

// ---------------- Kernel 4: finalize + apply BN affine in place ----------------
__global__ void norm_kernel(float* __restrict__ out,
                            const float* __restrict__ bn_gamma,
                            const float* __restrict__ bn_beta) {
    int e4 = blockIdx.x * 256 + threadIdx.x;
    int e = e4 * 4;
    int c = (e >> 14) & 63;
    const float npix = (float)(BB * H * W);
    float mean = g_sum[c] / npix;
    float var  = g_sqs[c] / npix - mean * mean;
    float rstd = rsqrtf(var + 1e-5f);
    float a  = bn_gamma[c] * rstd;
    float sh = bn_beta[c] - mean * a;
    float4 v = *(float4*)(out + e);
    v.x = fmaf(v.x, a, sh);
    v.y = fmaf(v.y, a, sh);
    v.z = fmaf(v.z, a, sh);
    v.w = fmaf(v.w, a, sh);
    *(float4*)(out + e) = v;
}

// ---------------- launch ----------------
extern "C" void kernel_launch(void* const* d_in, const int* in_sizes, int n_in,
                              void* d_out, int out_size) {
    const float* x        = (const float*)d_in[0];
    const float* g_w      = (const float*)d_in[1];
    const float* g_b      = (const float*)d_in[2];
    const float* theta_w  = (const float*)d_in[3];
    const float* theta_b  = (const float*)d_in[4];
    const float* phi_w    = (const float*)d_in[5];
    const float* phi_b    = (const float*)d_in[6];
    const float* out_w    = (const float*)d_in[7];
    const float* out_b    = (const float*)d_in[8];
    const float* bn_gamma = (const float*)d_in[9];
    const float* bn_beta  = (const float*)d_in[10];
    float* out = (float*)d_out;

    qkv_kernel<<<dim3(128, BB), 128>>>(x, g_w, g_b, theta_w, theta_b, phi_w, phi_b);
    prep_zero<<<1, 64>>>();
    prep_pack<<<4, 256>>>(out_w);
    attn_kernel<<<dim3(64, BB), 256>>>();   // 4th launch -> profiled
    fuse_kernel<<<1024, 256>>>(x, out_b, out);
    norm_kernel<<<4096, 256>>>(out, bn_gamma, bn_beta);
}

// round 9
// speedup vs baseline: 1.4903x; 1.4903x over previous
#include <cuda_runtime.h>

#define BB 4
#define C 64
#define IC 16
#define H 128
#define W 128
#define DH 64
#define DW 64
#define NN 4096  // DH*DW

// ---------------- scratch (device globals; no allocation) ----------------
__device__ __align__(16) float g_q[BB*NN*IC];   // tf32(LOG2E*q) bits
__device__ __align__(16) float g_k[BB*IC*NN];   // transposed [b][ic][n], tf32 bits
__device__ __align__(16) float g_v[BB*NN*IC];
__device__ __align__(16) float g_y[BB*IC*NN];
__device__ __align__(16) unsigned long long g_wpk[C*IC];  // out_w packed pairs
__device__ float g_sum[C];
__device__ float g_sqs[C];

typedef unsigned long long ull;
typedef unsigned int uint;

__device__ __forceinline__ ull pk2(float x, float y) {
    ull r;
    asm("mov.b64 %0, {%1,%2};" : "=l"(r) : "f"(x), "f"(y));
    return r;
}
__device__ __forceinline__ void fma2(ull& d, ull a, ull b) {
    asm("fma.rn.f32x2 %0, %1, %2, %3;" : "=l"(d) : "l"(a), "l"(b), "l"(d));
}
__device__ __forceinline__ ull add2(ull a, ull b) {
    ull r;
    asm("add.rn.f32x2 %0, %1, %2;" : "=l"(r) : "l"(a), "l"(b));
    return r;
}
__device__ __forceinline__ float ex2f(float x) {
    float r;
    asm("ex2.approx.f32 %0, %1;" : "=f"(r) : "f"(x));
    return r;
}
__device__ __forceinline__ uint tf32c(float f) {
    uint r;
    asm("cvt.rna.tf32.f32 %0, %1;" : "=r"(r) : "f"(f));
    return r;
}
__device__ __forceinline__ void mma_tf32(float* c, const uint* a, uint b0, uint b1) {
    asm("mma.sync.aligned.m16n8k8.row.col.f32.tf32.tf32.f32 "
        "{%0,%1,%2,%3}, {%4,%5,%6,%7}, {%8,%9}, {%0,%1,%2,%3};"
        : "+f"(c[0]), "+f"(c[1]), "+f"(c[2]), "+f"(c[3])
        : "r"(a[0]), "r"(a[1]), "r"(a[2]), "r"(a[3]), "r"(b0), "r"(b1));
}
__device__ __forceinline__ void cpa16(uint dst, const void* src) {
    asm volatile("cp.async.ca.shared.global [%0], [%1], 16;" :: "r"(dst), "l"(src));
}

#define LOG2E 1.4426950408889634f

// ---------------- Kernel 1: downsample (odd-pixel pick) + Q/K/V projections ----------------
__global__ void qkv_kernel(const float* __restrict__ x,
                           const float* __restrict__ g_w,  const float* __restrict__ g_b,
                           const float* __restrict__ th_w, const float* __restrict__ th_b,
                           const float* __restrict__ ph_w, const float* __restrict__ ph_b) {
    __shared__ float xd_s[C][32];
    __shared__ float w_s[48][C];
    __shared__ float b_s[48];
    int b = blockIdx.y, tile = blockIdx.x, tid = threadIdx.x;

    for (int idx = tid; idx < 48 * C; idx += 128) {
        int o = idx >> 6, c = idx & 63;
        float w;
        if (o < 16)      w = th_w[o * C + c];
        else if (o < 32) w = ph_w[(o - 16) * C + c];
        else             w = g_w[(o - 32) * C + c];
        w_s[o][c] = w;
    }
    if (tid < 48)
        b_s[tid] = (tid < 16) ? th_b[tid] : ((tid < 32) ? ph_b[tid - 16] : g_b[tid - 32]);

    int n0 = tile * 32;
    for (int idx = tid; idx < C * 32; idx += 128) {
        int c = idx >> 5, p = idx & 31;
        int n = n0 + p;
        int i = n >> 6, j = n & 63;
        xd_s[c][p] = x[(((b * C + c) * H + 2 * i + 1) * W) + 2 * j + 1];
    }
    __syncthreads();

    int p = tid & 31, og = tid >> 5;
    int n = n0 + p;
    #pragma unroll
    for (int r = 0; r < 12; r++) {
        int o = og + 4 * r;
        float a0 = b_s[o], a1 = 0.f, a2 = 0.f, a3 = 0.f;
        #pragma unroll
        for (int c = 0; c < C; c += 4) {
            a0 = fmaf(w_s[o][c + 0], xd_s[c + 0][p], a0);
            a1 = fmaf(w_s[o][c + 1], xd_s[c + 1][p], a1);
            a2 = fmaf(w_s[o][c + 2], xd_s[c + 2][p], a2);
            a3 = fmaf(w_s[o][c + 3], xd_s[c + 3][p], a3);
        }
        float acc = (a0 + a1) + (a2 + a3);
        if (o < 16)      g_q[(b * NN + n) * IC + o] = __uint_as_float(tf32c(acc * LOG2E));
        else if (o < 32) g_k[(b * IC + (o - 16)) * NN + n] = __uint_as_float(tf32c(acc));
        else             g_v[(b * NN + n) * IC + (o - 32)] = acc;
    }
}

// ---------------- Kernel 1b: zero BN stats ----------------
__global__ void prep_zero() {
    int t = threadIdx.x;
    if (t < C) { g_sum[t] = 0.f; g_sqs[t] = 0.f; }
}

// ---------------- Kernel 1c: pack out_w into broadcast pairs ----------------
__global__ void prep_pack(const float* __restrict__ out_w) {
    int i = blockIdx.x * 256 + threadIdx.x;
    float w = out_w[i];
    g_wpk[i] = pk2(w, w);
}

// ---------------- Kernel 2: tensor-core flash attention ----------------
// grid (32, BB) = 128 CTAs (single wave), block 512 (16 warps). CTA = 128 queries.
// warp w: queries (w&7)*16..+15, key-half kh = w>>3. Double-buffered cp.async.
#define TK 128
#define KSP 136
#define QQ 128

struct AttnSmem {
    uint  ks[2][IC][KSP];                 // 17408 B
    __align__(16) float vs[2][TK][20];    // 20480 B
    float redY[2][QQ][17];                // 17408 B
    float redD[2][QQ];                    // 1024 B
};
#define ATTN_SMEM_BYTES sizeof(AttnSmem)

__global__ __launch_bounds__(512) void attn_kernel() {
    extern __shared__ __align__(16) char smem_raw[];
    AttnSmem& sm = *reinterpret_cast<AttnSmem*>(smem_raw);

    int b = blockIdx.y;
    int t = threadIdx.x;
    int w = t >> 5, lane = t & 31;
    int qw = w & 7, kh = w >> 3;
    int r = lane >> 2, cc = lane & 3;
    int n0 = blockIdx.x * QQ;

    // A fragments (Q) — pre-scaled + tf32-rounded by qkv_kernel
    uint A0[4], A1[4];
    {
        const uint* qb = (const uint*)(g_q + (b * NN + n0 + qw * 16) * IC);
        A0[0] = qb[ r      * IC + cc     ];
        A0[1] = qb[(r + 8) * IC + cc     ];
        A0[2] = qb[ r      * IC + cc + 4 ];
        A0[3] = qb[(r + 8) * IC + cc + 4 ];
        A1[0] = qb[ r      * IC + cc + 8 ];
        A1[1] = qb[(r + 8) * IC + cc + 8 ];
        A1[2] = qb[ r      * IC + cc + 12];
        A1[3] = qb[(r + 8) * IC + cc + 12];
    }

    float Y0[4] = {0.f, 0.f, 0.f, 0.f};
    float Y1[4] = {0.f, 0.f, 0.f, 0.f};
    float denr = 0.f, dens = 0.f;

    const float* kb = g_k + b * IC * NN;
    const float* vb = g_v + b * NN * IC;

    // one K chunk + one V chunk per thread (512 chunks each)
    int ic0s = t >> 5, col0 = t & 31;      // K: [ic][col4]
    int vkey0 = t >> 2, vseg0 = t & 3;     // V: [key][seg4]

    uint ks_d[2], vs_d[2];
    #pragma unroll
    for (int bf = 0; bf < 2; bf++) {
        ks_d[bf] = (uint)__cvta_generic_to_shared(&sm.ks[bf][ic0s][col0 * 4]);
        vs_d[bf] = (uint)__cvta_generic_to_shared(&sm.vs[bf][vkey0][vseg0 * 4]);
    }

    cpa16(ks_d[0], kb + ic0s * NN + col0 * 4);
    cpa16(vs_d[0], vb + vkey0 * IC + vseg0 * 4);
    asm volatile("cp.async.commit_group;");

    for (int it = 0; it < NN / TK; it++) {
        int cur = it & 1;
        if (it < NN / TK - 1) {
            int nxt = cur ^ 1, kt = (it + 1) * TK;
            cpa16(ks_d[nxt], kb + ic0s * NN + kt + col0 * 4);
            cpa16(vs_d[nxt], vb + (kt + vkey0) * IC + vseg0 * 4);
            asm volatile("cp.async.commit_group;");
            asm volatile("cp.async.wait_group 1;");
        } else {
            asm volatile("cp.async.wait_group 0;");
        }
        __syncthreads();

        #pragma unroll
        for (int nt = 0; nt < 8; nt++) {
            int key0 = kh * 64 + nt * 8;
            float S[4] = {0.f, 0.f, 0.f, 0.f};
            mma_tf32(S, A0, sm.ks[cur][cc][key0 + r],     sm.ks[cur][cc + 4][key0 + r]);
            mma_tf32(S, A1, sm.ks[cur][cc + 8][key0 + r], sm.ks[cur][cc + 12][key0 + r]);

            float e0 = ex2f(S[0]);
            float e1 = ex2f(S[1]);
            float e2 = ex2f(S[2]);
            float e3 = ex2f(S[3]);
            denr += e0 + e1;
            dens += e2 + e3;

            uint P[4];
            P[0] = __float_as_uint(e0);
            P[1] = __float_as_uint(e2);
            P[2] = __float_as_uint(e1);
            P[3] = __float_as_uint(e3);
            int ka = key0 + 2 * cc;
            mma_tf32(Y0, P, __float_as_uint(sm.vs[cur][ka][r]),
                            __float_as_uint(sm.vs[cur][ka + 1][r]));
            mma_tf32(Y1, P, __float_as_uint(sm.vs[cur][ka][r + 8]),
                            __float_as_uint(sm.vs[cur][ka + 1][r + 8]));
        }
        __syncthreads();
    }

    denr += __shfl_xor_sync(0xffffffffu, denr, 1);
    denr += __shfl_xor_sync(0xffffffffu, denr, 2);
    dens += __shfl_xor_sync(0xffffffffu, dens, 1);
    dens += __shfl_xor_sync(0xffffffffu, dens, 2);

    {
        int q0 = qw * 16 + r, q1 = q0 + 8;
        sm.redY[kh][q0][2 * cc]     = Y0[0];
        sm.redY[kh][q0][2 * cc + 1] = Y0[1];
        sm.redY[kh][q1][2 * cc]     = Y0[2];
        sm.redY[kh][q1][2 * cc + 1] = Y0[3];
        sm.redY[kh][q0][8 + 2 * cc]     = Y1[0];
        sm.redY[kh][q0][8 + 2 * cc + 1] = Y1[1];
        sm.redY[kh][q1][8 + 2 * cc]     = Y1[2];
        sm.redY[kh][q1][8 + 2 * cc + 1] = Y1[3];
        if (cc == 0) {
            sm.redD[kh][q0] = denr;
            sm.redD[kh][q1] = dens;
        }
    }
    __syncthreads();

    {
        int q = t >> 2, ic = (t & 3) * 4;
        float inv = 1.0f / (sm.redD[0][q] + sm.redD[1][q]);
        #pragma unroll
        for (int j = 0; j < 4; j++) {
            float v = (sm.redY[0][q][ic + j] + sm.redY[1][q][ic + j]) * inv;
            g_y[(b * IC + ic + j) * NN + n0 + q] = v;
        }
    }
}

// ---------------- Kernel 3: upsample + out-proj + residual (f32x2) ----------------
__global__ void fuse_kernel(const float* __restrict__ x,
                            const float* __restrict__ out_b,
                            float* __restrict__ out) {
    __shared__ __align__(8) float yup[IC][64];
    __shared__ ull wsm2[C][IC];
    __shared__ float bsm[C];
    int bx = blockIdx.x;
    int b  = bx >> 8;
    int row = (bx >> 1) & 127;
    int jh = bx & 1;
    int t = threadIdx.x;

    #pragma unroll
    for (int i = 0; i < 4; i++) {
        int idx = t + 256 * i;
        wsm2[idx >> 4][idx & 15] = g_wpk[idx];
    }
    if (t < C) bsm[t] = out_b[t];

    float fi = 0.5f * row - 0.5f;
    int r0 = (int)floorf(fi);
    float wi = fi - (float)r0;
    int r1 = min(r0 + 1, DH - 1);
    r0 = max(r0, 0);

    for (int idx = t; idx < IC * 64; idx += 256) {
        int ic = idx >> 6, p = idx & 63;
        int j = jh * 64 + p;
        float fj = 0.5f * j - 0.5f;
        int c0 = (int)floorf(fj);
        float wj = fj - (float)c0;
        int c1 = min(c0 + 1, DW - 1);
        c0 = max(c0, 0);
        const float* yp = g_y + (b * IC + ic) * NN;
        float v00 = yp[r0 * DW + c0], v01 = yp[r0 * DW + c1];
        float v10 = yp[r1 * DW + c0], v11 = yp[r1 * DW + c1];
        yup[ic][p] = (1.f - wi) * fmaf(wj, v01 - v00, v00)
                   +        wi  * fmaf(wj, v11 - v10, v10);
    }
    __syncthreads();

    int p2 = t & 31, cg = t >> 5;
    ull yv[16];
    #pragma unroll
    for (int i2 = 0; i2 < 16; i2++) yv[i2] = *(const ull*)&yup[i2][2 * p2];

    #pragma unroll
    for (int k = 0; k < 8; k++) {
        int c = cg * 8 + k;
        float bb = bsm[c];
        ull acc = pk2(bb, bb);
        #pragma unroll
        for (int i2 = 0; i2 < 16; i2++) fma2(acc, wsm2[c][i2], yv[i2]);
        int gi = ((b * C + c) * H + row) * W + jh * 64 + 2 * p2;
        ull xv = *(const ull*)(x + gi);
        acc = add2(acc, xv);
        *(ull*)(out + gi) = acc;
    }
}

// ---------------- Kernel 3b: BN batch stats over out ----------------
__global__ void stats_kernel(const float* __restrict__ out) {
    __shared__ float s1s[8], s2s[8];
    int c = blockIdx.x, sl = blockIdx.y, t = threadIdx.x;
    float s1 = 0.f, s2 = 0.f;
    #pragma unroll
    for (int b = 0; b < BB; b++) {
        const float4* p = (const float4*)(out + (((b * C + c) << 14) + sl * 1024));
        float4 v = p[t];
        s1 += (v.x + v.y) + (v.z + v.w);
        s2 += fmaf(v.x, v.x, v.y * v.y) + fmaf(v.z, v.z, v.w * v.w);
    }
    #pragma unroll
    for (int off = 16; off; off >>= 1) {
        s1 += __shfl_down_sync(0xffffffffu, s1, off);
        s2 += __shfl_down_sync(0xffffffffu, s2, off);
    }
    int w = t >> 5;
    if ((t & 31) == 0) { s1s[w] = s1; s2s[w] = s2; }
    __syncthreads();
    if (t == 0) {
        float a1 = 0.f, a2 = 0.f;
        #pragma unroll
        for (int i = 0; i < 8; i++) { a1 += s1s[i]; a2 += s2s[i]; }
        atomicAdd(&g_sum[c], a1);
        atomicAdd(&g_sqs[c], a2);
    }
}

// ---------------- Kernel 4: finalize + apply BN affine in place ----------------
__global__ void norm_kernel(float* __restrict__ out,
                            const float* __restrict__ bn_gamma,
                            const float* __restrict__ bn_beta) {
    int e4 = blockIdx.x * 256 + threadIdx.x;
    int e = e4 * 4;
    int c = (e >> 14) & 63;
    const float npix = (float)(BB * H * W);
    float mean = g_sum[c] / npix;
    float var  = g_sqs[c] / npix - mean * mean;
    float rstd = rsqrtf(var + 1e-5f);
    float a  = bn_gamma[c] * rstd;
    float sh = bn_beta[c] - mean * a;
    float4 v = *(float4*)(out + e);
    v.x = fmaf(v.x, a, sh);
    v.y = fmaf(v.y, a, sh);
    v.z = fmaf(v.z, a, sh);
    v.w = fmaf(v.w, a, sh);
    *(float4*)(out + e) = v;
}

// ---------------- launch ----------------
extern "C" void kernel_launch(void* const* d_in, const int* in_sizes, int n_in,
                              void* d_out, int out_size) {
    const float* x        = (const float*)d_in[0];
    const float* g_w      = (const float*)d_in[1];
    const float* g_b      = (const float*)d_in[2];
    const float* theta_w  = (const float*)d_in[3];
    const float* theta_b  = (const float*)d_in[4];
    const float* phi_w    = (const float*)d_in[5];
    const float* phi_b    = (const float*)d_in[6];
    const float* out_w    = (const float*)d_in[7];
    const float* out_b    = (const float*)d_in[8];
    const float* bn_gamma = (const float*)d_in[9];
    const float* bn_beta  = (const float*)d_in[10];
    float* out = (float*)d_out;

    static bool attr_done = false;
    if (!attr_done) {
        cudaFuncSetAttribute(attn_kernel,
                             cudaFuncAttributeMaxDynamicSharedMemorySize,
                             (int)ATTN_SMEM_BYTES);
        attr_done = true;
    }

    qkv_kernel<<<dim3(128, BB), 128>>>(x, g_w, g_b, theta_w, theta_b, phi_w, phi_b);
    prep_zero<<<1, 64>>>();
    prep_pack<<<4, 256>>>(out_w);
    attn_kernel<<<dim3(32, BB), 512, ATTN_SMEM_BYTES>>>();   // 4th launch -> profiled
    fuse_kernel<<<1024, 256>>>(x, out_b, out);
    stats_kernel<<<dim3(C, 16), 256>>>(out);
    norm_kernel<<<4096, 256>>>(out, bn_gamma, bn_beta);
}